// round 6
// baseline (speedup 1.0000x reference)
#include <cuda_runtime.h>
#include <cuda_bf16.h>

#define FULL_MASK 0xffffffffu

static constexpr int Bb = 256;
static constexpr int Tt = 2048;
static constexpr float INV_LN2 = 1.4426950408889634f;
static constexpr float LN2     = 0.6931471805599453f;

__device__ float g_s12[Bb];   // s1+s2 per batch, written by score kernel

__device__ __forceinline__ float ex2f(float x) {
    float r; asm("ex2.approx.f32 %0, %1;" : "=f"(r) : "f"(x)); return r;
}
__device__ __forceinline__ float lg2f(float x) {
    float r; asm("lg2.approx.f32 %0, %1;" : "=f"(r) : "f"(x)); return r;
}
__device__ __forceinline__ float rcpf(float x) {
    float r; asm("rcp.approx.f32 %0, %1;" : "=f"(r) : "f"(x)); return r;
}
__device__ __forceinline__ unsigned cvt_bf16x2(float hi, float lo) {
    unsigned r; asm("cvt.rn.bf16x2.f32 %0, %1, %2;" : "=r"(r) : "f"(hi), "f"(lo)); return r;
}
__device__ __forceinline__ unsigned hfma2b(unsigned a, unsigned b, unsigned c) {
    unsigned r; asm("fma.rn.bf16x2 %0, %1, %2, %3;" : "=r"(r) : "r"(a), "r"(b), "r"(c)); return r;
}
__device__ __forceinline__ unsigned hadd2b(unsigned a, unsigned b) {
    unsigned r; asm("add.rn.bf16x2 %0, %1, %2;" : "=r"(r) : "r"(a), "r"(b)); return r;
}
__device__ __forceinline__ float bf_lo(unsigned v) { return __uint_as_float(v << 16); }
__device__ __forceinline__ float bf_hi(unsigned v) { return __uint_as_float(v & 0xFFFF0000u); }

// ============================================================================
// Kernel 1: scores (s1 emission + s2 transition), fully parallel over (b,t)
// ============================================================================
__global__ __launch_bounds__(512) void crf_scores(
    const float* __restrict__ p,
    const int*   __restrict__ y,
    const int*   __restrict__ mask,
    const float* __restrict__ tr)
{
    const int b   = blockIdx.x;
    const int tid = threadIdx.x;
    const int l   = tid & 31;
    const int w   = tid >> 5;          // 16 warps

    __shared__ short labs[Tt];
    __shared__ int   sL;
    __shared__ float red[16];

    if (tid == 0) sL = 0;
    __syncthreads();

    int cnt = 0;
    const int* mb = mask + (size_t)b * Tt;
    for (int t = tid; t < Tt; t += 512) cnt += (mb[t] == 0);
    #pragma unroll
    for (int o = 16; o; o >>= 1) cnt += __shfl_xor_sync(FULL_MASK, cnt, o);
    if (l == 0) atomicAdd(&sL, cnt);
    __syncthreads();
    const int L = sL;

    const int2* yb = reinterpret_cast<const int2*>(y) + (size_t)b * Tt * 32 + l;
    float s1 = 0.f;
    for (int k = 0; k < 128; ++k) {
        int t = w * 128 + k;
        int2 yv = yb[(size_t)t * 32];
        unsigned balx = __ballot_sync(FULL_MASK, yv.x != 0);
        unsigned baly = __ballot_sync(FULL_MASK, yv.y != 0);
        int srcl = __ffs(balx | baly) - 1;
        int lab  = 2 * srcl + ((baly >> srcl) & 1);
        if (l == 0) labs[t] = (short)lab;
        if (l == srcl && t < L)
            s1 += __ldg(&p[((size_t)(b * Tt + t) << 6) + lab]);
    }
    __syncthreads();

    float s2 = 0.f;
    for (int t = tid; t < L - 1; t += 512)
        s2 += __ldg(&tr[(int)labs[t] * 64 + (int)labs[t + 1]]);

    float s = s1 + s2;
    #pragma unroll
    for (int o = 16; o; o >>= 1) s += __shfl_xor_sync(FULL_MASK, s, o);
    if (l == 0) red[w] = s;
    __syncthreads();
    if (tid == 0) {
        float tot = 0.f;
        #pragma unroll
        for (int i = 0; i < 16; ++i) tot += red[i];
        g_s12[b] = tot;
    }
}

// ============================================================================
// Kernel 2: forward recursion, pure exp domain, TWO chains per warp.
// 128 single-warp blocks; block x handles batches x and x+128.
// Renorm by A[0] via RCP (off-chain lg2 bookkeeping), em precomputed from p.
// ============================================================================
__global__ __launch_bounds__(32, 1) void crf_forward(
    const float* __restrict__ p,
    const int*   __restrict__ mask,
    const float* __restrict__ tr,
    float*       __restrict__ out)
{
    const int l  = threadIdx.x;
    const int b0 = blockIdx.x;
    const int b1 = blockIdx.x + Bb / 2;

    __shared__ unsigned shA[2][2][64];  // [chain][parity][e], dup bf16x2 {A,A}

    // E = exp(transition), columns (d0,d1) packed bf16x2
    unsigned Eb[64];
    const float2* trp = reinterpret_cast<const float2*>(tr);
    #pragma unroll
    for (int e = 0; e < 64; ++e) {
        float2 v = trp[e * 32 + l];
        Eb[e] = cvt_bf16x2(__expf(v.y), __expf(v.x));
    }

    // sequence lengths for both chains
    int c0i = 0, c1i = 0;
    const int* mb0 = mask + (size_t)b0 * Tt;
    const int* mb1 = mask + (size_t)b1 * Tt;
    #pragma unroll 8
    for (int t = l; t < Tt; t += 32) { c0i += (mb0[t] == 0); c1i += (mb1[t] == 0); }
    #pragma unroll
    for (int o = 16; o; o >>= 1) {
        c0i += __shfl_xor_sync(FULL_MASK, c0i, o);
        c1i += __shfl_xor_sync(FULL_MASK, c1i, o);
    }
    const int L0 = c0i, L1 = c1i;
    const int Lmax = (L0 > L1) ? L0 : L1;

    const float2* pb0 = reinterpret_cast<const float2*>(p) + (size_t)b0 * Tt * 32 + l;
    const float2* pb1 = pb0 + (size_t)(Bb / 2) * Tt * 32;

    // ---- init t=0
    float2 q0 = pb0[0], q1 = pb1[0];
    float n0 = __shfl_sync(FULL_MASK, q0.x, 0) * INV_LN2;
    float n1 = __shfl_sync(FULL_MASK, q1.x, 0) * INV_LN2;
    float vx0 = ex2f(fmaf(q0.x, INV_LN2, -n0));
    float vy0 = ex2f(fmaf(q0.y, INV_LN2, -n0));
    float vx1 = ex2f(fmaf(q1.x, INV_LN2, -n1));
    float vy1 = ex2f(fmaf(q1.y, INV_LN2, -n1));
    float logC0 = n0, logC1 = n1;
    reinterpret_cast<uint2*>(shA[0][0])[l] =
        make_uint2(cvt_bf16x2(vx0, vx0), cvt_bf16x2(vy0, vy0));
    reinterpret_cast<uint2*>(shA[1][0])[l] =
        make_uint2(cvt_bf16x2(vx1, vx1), cvt_bf16x2(vy1, vy1));
    __syncwarp();

    // prefetch p, distance 4, both chains
    float2 pf0[4], pf1[4];
    #pragma unroll
    for (int i = 0; i < 4; ++i) {
        pf0[i] = pb0[(size_t)(1 + i) * 32];
        pf1[i] = pb1[(size_t)(1 + i) * 32];
    }

    for (int tb = 1; tb < Lmax; tb += 4) {
        #pragma unroll
        for (int i = 0; i < 4; ++i) {
            const int t = tb + i;
            if (t >= Lmax) break;                  // warp-uniform
            const int q  = t & 1;
            const int qp = q ^ 1;

            float2 pt0 = pf0[i], pt1 = pf1[i];
            int tn = t + 4; if (tn > Tt - 1) tn = Tt - 1;
            pf0[i] = pb0[(size_t)tn * 32];
            pf1[i] = pb1[(size_t)tn * 32];

            // em = exp(p_t): depends only on p — fully off the recurrence chain
            float em0x = ex2f(pt0.x * INV_LN2);
            float em0y = ex2f(pt0.y * INV_LN2);
            float em1x = ex2f(pt1.x * INV_LN2);
            float em1y = ex2f(pt1.y * INV_LN2);

            // normalizers: r = A_{t-1}[0] (broadcast LDS), invert off-chain-ish
            float r0 = bf_lo(shA[0][qp][0]);
            float r1 = bf_lo(shA[1][qp][0]);
            float ri0 = rcpf(r0);
            float ri1 = rcpf(r1);

            // dual dots: s[d] = sum_e A[e] * E[e][d]
            const uint4* s0 = reinterpret_cast<const uint4*>(shA[0][qp]);
            const uint4* s1 = reinterpret_cast<const uint4*>(shA[1][qp]);
            unsigned A0=0,A1=0,A2=0,A3=0,A4=0,A5=0,A6=0,A7=0;
            unsigned B0=0,B1=0,B2=0,B3=0,B4=0,B5=0,B6=0,B7=0;
            #pragma unroll
            for (int g = 0; g < 8; ++g) {
                uint4 u0 = s0[2 * g];
                uint4 w0 = s0[2 * g + 1];
                uint4 u1 = s1[2 * g];
                uint4 w1 = s1[2 * g + 1];
                A0 = hfma2b(u0.x, Eb[8 * g + 0], A0);
                B0 = hfma2b(u1.x, Eb[8 * g + 0], B0);
                A1 = hfma2b(u0.y, Eb[8 * g + 1], A1);
                B1 = hfma2b(u1.y, Eb[8 * g + 1], B1);
                A2 = hfma2b(u0.z, Eb[8 * g + 2], A2);
                B2 = hfma2b(u1.z, Eb[8 * g + 2], B2);
                A3 = hfma2b(u0.w, Eb[8 * g + 3], A3);
                B3 = hfma2b(u1.w, Eb[8 * g + 3], B3);
                A4 = hfma2b(w0.x, Eb[8 * g + 4], A4);
                B4 = hfma2b(w1.x, Eb[8 * g + 4], B4);
                A5 = hfma2b(w0.y, Eb[8 * g + 5], A5);
                B5 = hfma2b(w1.y, Eb[8 * g + 5], B5);
                A6 = hfma2b(w0.z, Eb[8 * g + 6], A6);
                B6 = hfma2b(w1.z, Eb[8 * g + 6], B6);
                A7 = hfma2b(w0.w, Eb[8 * g + 7], A7);
                B7 = hfma2b(w1.w, Eb[8 * g + 7], B7);
            }
            unsigned Aa = hadd2b(A0, A1), Ab = hadd2b(A2, A3);
            unsigned Ac = hadd2b(A4, A5), Ad = hadd2b(A6, A7);
            unsigned Ba = hadd2b(B0, B1), Bb2 = hadd2b(B2, B3);
            unsigned Bc = hadd2b(B4, B5), Bd = hadd2b(B6, B7);
            float sx0 = (bf_lo(Aa) + bf_lo(Ab)) + (bf_lo(Ac) + bf_lo(Ad));
            float sy0 = (bf_hi(Aa) + bf_hi(Ab)) + (bf_hi(Ac) + bf_hi(Ad));
            float sx1 = (bf_lo(Ba) + bf_lo(Bb2)) + (bf_lo(Bc) + bf_lo(Bd));
            float sy1 = (bf_hi(Ba) + bf_hi(Bb2)) + (bf_hi(Bc) + bf_hi(Bd));

            const bool ok0 = t < L0;
            const bool ok1 = t < L1;

            float nx0 = sx0 * em0x * ri0;
            float ny0 = sy0 * em0y * ri0;
            float nx1 = sx1 * em1x * ri1;
            float ny1 = sy1 * em1y * ri1;
            vx0 = ok0 ? nx0 : vx0;  vy0 = ok0 ? ny0 : vy0;
            vx1 = ok1 ? nx1 : vx1;  vy1 = ok1 ? ny1 : vy1;
            logC0 += ok0 ? lg2f(r0) : 0.f;
            logC1 += ok1 ? lg2f(r1) : 0.f;

            reinterpret_cast<uint2*>(shA[0][q])[l] =
                make_uint2(cvt_bf16x2(vx0, vx0), cvt_bf16x2(vy0, vy0));
            reinterpret_cast<uint2*>(shA[1][q])[l] =
                make_uint2(cvt_bf16x2(vx1, vx1), cvt_bf16x2(vy1, vy1));
            __syncwarp();
        }
    }

    // ---- finalize both chains: logZ = LN2 * (log2(sum_d A) + logC)
    float s0f = vx0 + vy0;
    float s1f = vx1 + vy1;
    #pragma unroll
    for (int o = 16; o; o >>= 1) {
        s0f += __shfl_xor_sync(FULL_MASK, s0f, o);
        s1f += __shfl_xor_sync(FULL_MASK, s1f, o);
    }
    if (l == 0) {
        out[b0] = LN2 * (lg2f(s0f) + logC0) - g_s12[b0];
        out[b1] = LN2 * (lg2f(s1f) + logC1) - g_s12[b1];
    }
}

extern "C" void kernel_launch(void* const* d_in, const int* in_sizes, int n_in,
                              void* d_out, int out_size) {
    const float* p    = (const float*)d_in[0];
    const int*   y    = (const int*)d_in[1];
    const int*   mask = (const int*)d_in[2];
    const float* tr   = (const float*)d_in[3];
    float* out = (float*)d_out;

    crf_scores<<<Bb, 512>>>(p, y, mask, tr);
    crf_forward<<<Bb / 2, 32>>>(p, mask, tr, out);
}

// round 7
// speedup vs baseline: 6.1475x; 6.1475x over previous
#include <cuda_runtime.h>
#include <cuda_bf16.h>

#define FULL_MASK 0xffffffffu

static constexpr int Bb = 256;
static constexpr int Tt = 2048;
static constexpr int NCH = 16;          // chunks per sequence
static constexpr int CLEN = Tt / NCH;   // 128 tokens per chunk
static constexpr int WARM = 32;         // warm-up offset (31 contraction steps)
static constexpr float INV_LN2 = 1.4426950408889634f;
static constexpr float LN2     = 0.6931471805599453f;

__device__ float g_s12[Bb];           // s1+s2 per batch
__device__ int   g_len[Bb];           // sequence lengths
__device__ float g_gpart[Bb * NCH];   // per-chunk log-scale partial sums
__device__ float g_snap[Bb];          // lg2(sum A_{L-1}) from owning chunk

__device__ __forceinline__ float ex2f(float x) {
    float r; asm("ex2.approx.f32 %0, %1;" : "=f"(r) : "f"(x)); return r;
}
__device__ __forceinline__ float lg2f(float x) {
    float r; asm("lg2.approx.f32 %0, %1;" : "=f"(r) : "f"(x)); return r;
}
__device__ __forceinline__ float rcpf(float x) {
    float r; asm("rcp.approx.f32 %0, %1;" : "=f"(r) : "f"(x)); return r;
}
__device__ __forceinline__ unsigned cvt_bf16x2(float hi, float lo) {
    unsigned r; asm("cvt.rn.bf16x2.f32 %0, %1, %2;" : "=r"(r) : "f"(hi), "f"(lo)); return r;
}
__device__ __forceinline__ unsigned hfma2b(unsigned a, unsigned b, unsigned c) {
    unsigned r; asm("fma.rn.bf16x2 %0, %1, %2, %3;" : "=r"(r) : "r"(a), "r"(b), "r"(c)); return r;
}
__device__ __forceinline__ unsigned hadd2b(unsigned a, unsigned b) {
    unsigned r; asm("add.rn.bf16x2 %0, %1, %2;" : "=r"(r) : "r"(a), "r"(b)); return r;
}
__device__ __forceinline__ float bf_lo(unsigned v) { return __uint_as_float(v << 16); }
__device__ __forceinline__ float bf_hi(unsigned v) { return __uint_as_float(v & 0xFFFF0000u); }

// ============================================================================
// Kernel 1: scores (s1 + s2) and sequence lengths. Parallel over (b, t).
// ============================================================================
__global__ __launch_bounds__(512) void crf_scores(
    const float* __restrict__ p,
    const int*   __restrict__ y,
    const int*   __restrict__ mask,
    const float* __restrict__ tr)
{
    const int b   = blockIdx.x;
    const int tid = threadIdx.x;
    const int l   = tid & 31;
    const int w   = tid >> 5;

    __shared__ short labs[Tt];
    __shared__ int   sL;
    __shared__ float red[16];

    if (tid == 0) sL = 0;
    __syncthreads();

    int cnt = 0;
    const int* mb = mask + (size_t)b * Tt;
    for (int t = tid; t < Tt; t += 512) cnt += (mb[t] == 0);
    #pragma unroll
    for (int o = 16; o; o >>= 1) cnt += __shfl_xor_sync(FULL_MASK, cnt, o);
    if (l == 0) atomicAdd(&sL, cnt);
    __syncthreads();
    const int L = sL;
    if (tid == 0) g_len[b] = L;

    const int2* yb = reinterpret_cast<const int2*>(y) + (size_t)b * Tt * 32 + l;
    float s1 = 0.f;
    for (int k = 0; k < 128; ++k) {
        int t = w * 128 + k;
        int2 yv = yb[(size_t)t * 32];
        unsigned balx = __ballot_sync(FULL_MASK, yv.x != 0);
        unsigned baly = __ballot_sync(FULL_MASK, yv.y != 0);
        int srcl = __ffs(balx | baly) - 1;
        int lab  = 2 * srcl + ((baly >> srcl) & 1);
        if (l == 0) labs[t] = (short)lab;
        if (l == srcl && t < L)
            s1 += __ldg(&p[((size_t)(b * Tt + t) << 6) + lab]);
    }
    __syncthreads();

    float s2 = 0.f;
    for (int t = tid; t < L - 1; t += 512)
        s2 += __ldg(&tr[(int)labs[t] * 64 + (int)labs[t + 1]]);

    float s = s1 + s2;
    #pragma unroll
    for (int o = 16; o; o >>= 1) s += __shfl_xor_sync(FULL_MASK, s, o);
    if (l == 0) red[w] = s;
    __syncthreads();
    if (tid == 0) {
        float tot = 0.f;
        #pragma unroll
        for (int i = 0; i < 16; ++i) tot += red[i];
        g_s12[b] = tot;
    }
}

// ============================================================================
// Kernel 2: chunked forward recursion. One warp = one (batch, chunk).
// Chunk j>0 warms up 31 steps from a uniform vector (Birkhoff contraction
// 0.37^31 ~ 5e-14 -> canonical trajectory); renormalized recursion is
// scale-invariant so per-step r_t values telescope across chunks.
// ============================================================================
__global__ __launch_bounds__(128) void crf_forward_chunks(
    const float* __restrict__ p,
    const float* __restrict__ tr)
{
    const int wid = threadIdx.x >> 5;
    const int l   = threadIdx.x & 31;
    const int gw  = blockIdx.x * 4 + wid;   // 0 .. 4095
    const int b   = gw >> 4;                // batch
    const int j   = gw & (NCH - 1);         // chunk
    const int s   = j * CLEN;               // chunk start token

    __shared__ unsigned shAall[4][2][64];
    unsigned (*sh)[64] = shAall[wid];

    // E = exp(transition), columns (2l, 2l+1) packed bf16x2
    unsigned Eb[64];
    const float2* trp = reinterpret_cast<const float2*>(tr);
    #pragma unroll
    for (int e = 0; e < 64; ++e) {
        float2 v = trp[e * 32 + l];
        Eb[e] = cvt_bf16x2(__expf(v.y), __expf(v.x));
    }

    const int L = g_len[b];
    const float2* pb = reinterpret_cast<const float2*>(p) + (size_t)b * Tt * 32 + l;

    // step k computes token t = t0 + k, for k = 1..n
    int t0, n, gstart;
    if (j == 0) {
        t0 = 0;
        n = (L < CLEN ? L : CLEN) - 1;      // tokens 1..127 (L >= 1024)
        gstart = 1;
    } else {
        t0 = s - WARM;
        int span = L - s;                    // valid tokens in this chunk
        if (span > CLEN) span = CLEN;
        n = (span > 0) ? (WARM - 1 + span) : 0;
        gstart = WARM;                       // k >= WARM are real chunk tokens
    }

    // init A at time t0
    float vx, vy;
    float logC = 0.f;
    if (j == 0) {
        float2 q0 = pb[0];
        float c0 = __shfl_sync(FULL_MASK, q0.x, 0) * INV_LN2;
        vx = ex2f(fmaf(q0.x, INV_LN2, -c0));
        vy = ex2f(fmaf(q0.y, INV_LN2, -c0));
        logC = c0;
    } else {
        vx = 1.f; vy = 1.f;
    }
    reinterpret_cast<uint2*>(sh[0])[l] =
        make_uint2(cvt_bf16x2(vx, vx), cvt_bf16x2(vy, vy));
    __syncwarp();

    // prefetch p, distance 4
    float2 pf[4];
    #pragma unroll
    for (int i = 0; i < 4; ++i) {
        int tt = t0 + 1 + i; if (tt > Tt - 1) tt = Tt - 1;
        pf[i] = pb[(size_t)tt * 32];
    }

    for (int kb = 1; kb <= n; kb += 4) {
        #pragma unroll
        for (int i = 0; i < 4; ++i) {
            const int k = kb + i;
            if (k > n) break;                       // warp-uniform
            const int q  = k & 1;
            const int qp = q ^ 1;

            float2 pt = pf[i];
            int tn = t0 + k + 4; if (tn > Tt - 1) tn = Tt - 1;
            pf[i] = pb[(size_t)tn * 32];

            // em depends only on p: off the recurrence chain
            float emx = ex2f(pt.x * INV_LN2);
            float emy = ex2f(pt.y * INV_LN2);

            float r  = bf_lo(sh[qp][0]);
            float ri = rcpf(r);

            const uint4* sa = reinterpret_cast<const uint4*>(sh[qp]);
            unsigned A0=0,A1=0,A2=0,A3=0,A4=0,A5=0,A6=0,A7=0;
            #pragma unroll
            for (int g = 0; g < 8; ++g) {
                uint4 u = sa[2 * g];
                uint4 w = sa[2 * g + 1];
                A0 = hfma2b(u.x, Eb[8 * g + 0], A0);
                A1 = hfma2b(u.y, Eb[8 * g + 1], A1);
                A2 = hfma2b(u.z, Eb[8 * g + 2], A2);
                A3 = hfma2b(u.w, Eb[8 * g + 3], A3);
                A4 = hfma2b(w.x, Eb[8 * g + 4], A4);
                A5 = hfma2b(w.y, Eb[8 * g + 5], A5);
                A6 = hfma2b(w.z, Eb[8 * g + 6], A6);
                A7 = hfma2b(w.w, Eb[8 * g + 7], A7);
            }
            unsigned Sa = hadd2b(A0, A1), Sb = hadd2b(A2, A3);
            unsigned Sc = hadd2b(A4, A5), Sd = hadd2b(A6, A7);
            float sx = (bf_lo(Sa) + bf_lo(Sb)) + (bf_lo(Sc) + bf_lo(Sd));
            float sy = (bf_hi(Sa) + bf_hi(Sb)) + (bf_hi(Sc) + bf_hi(Sd));

            vx = sx * emx * ri;
            vy = sy * emy * ri;
            logC += (k >= gstart) ? lg2f(r) : 0.f;

            reinterpret_cast<uint2*>(sh[q])[l] =
                make_uint2(cvt_bf16x2(vx, vx), cvt_bf16x2(vy, vy));
            __syncwarp();
        }
    }

    // owner chunk (contains t = L-1): final vx,vy are A_{L-1}
    const bool owner = (L > s) && (L <= s + CLEN);
    float fs = vx + vy;
    #pragma unroll
    for (int o = 16; o; o >>= 1) fs += __shfl_xor_sync(FULL_MASK, fs, o);
    if (l == 0) {
        g_gpart[b * NCH + j] = logC;
        if (owner) g_snap[b] = lg2f(fs);
    }
}

// ============================================================================
// Kernel 3: combine per-chunk partials (deterministic fixed-order sum).
// ============================================================================
__global__ __launch_bounds__(256) void crf_combine(float* __restrict__ out)
{
    const int b = threadIdx.x;
    float g = 0.f;
    #pragma unroll
    for (int jj = 0; jj < NCH; ++jj) g += g_gpart[b * NCH + jj];
    out[b] = LN2 * (g_snap[b] + g) - g_s12[b];
}

extern "C" void kernel_launch(void* const* d_in, const int* in_sizes, int n_in,
                              void* d_out, int out_size) {
    const float* p    = (const float*)d_in[0];
    const int*   y    = (const int*)d_in[1];
    const int*   mask = (const int*)d_in[2];
    const float* tr   = (const float*)d_in[3];
    float* out = (float*)d_out;

    crf_scores<<<Bb, 512>>>(p, y, mask, tr);
    crf_forward_chunks<<<Bb * NCH / 4, 128>>>(p, tr);
    crf_combine<<<1, 256>>>(out);
}